// round 2
// baseline (speedup 1.0000x reference)
#include <cuda_runtime.h>

#define N_NODES  100000
#define N_EDGES  1600000
#define IN_CH    128
#define HID      128
#define OUT_CH   64
#define N_GRAPHS 512

static const int NB_SCAN = (N_NODES + 1023) / 1024;   // 98

// ---------------- scratch (device globals: no allocation allowed) ----------
__device__ int    g_deg[N_NODES];
__device__ int    g_incl[N_NODES];
__device__ int    g_bsum[128];
__device__ int    g_rowptr[N_NODES + 1];
__device__ int    g_cursor[N_NODES];
__device__ int    g_srcidx[N_EDGES];
__device__ float  g_dinv[N_NODES];
__device__ float4 g_hs[N_NODES * (HID / 4)];   // GEMM output, pre-scaled by dinv[row]
__device__ float4 g_h2[N_NODES * (HID / 4)];   // conv output
__device__ float  g_pool[N_GRAPHS * HID];
__device__ float  g_mlp [N_GRAPHS * HID];

// ---------------- degree / CSR build ---------------------------------------
__global__ void k_zero_deg() {
    int i = blockIdx.x * blockDim.x + threadIdx.x;
    if (i < N_NODES) g_deg[i] = 0;
}

__global__ void k_count(const int* __restrict__ ei) {
    int e = blockIdx.x * blockDim.x + threadIdx.x;
    if (e < N_EDGES) {
        int d = ei[N_EDGES + e];
        atomicAdd(&g_deg[d], 1);
    }
}

__global__ void k_dinv() {
    int i = blockIdx.x * blockDim.x + threadIdx.x;
    if (i < N_NODES) g_dinv[i] = rsqrtf((float)(g_deg[i] + 1));   // +1: self loop
}

__global__ void k_scan1() {
    __shared__ int s[1024];
    int t = threadIdx.x;
    int i = blockIdx.x * 1024 + t;
    int v = (i < N_NODES) ? g_deg[i] : 0;
    s[t] = v;
    __syncthreads();
    for (int off = 1; off < 1024; off <<= 1) {
        int a = (t >= off) ? s[t - off] : 0;
        __syncthreads();
        s[t] += a;
        __syncthreads();
    }
    if (i < N_NODES) g_incl[i] = s[t];
    if (t == 1023) g_bsum[blockIdx.x] = s[1023];
}

__global__ void k_scan2(int nb) {
    // single thread: exclusive scan over ~98 block sums
    int acc = 0;
    for (int b = 0; b < nb; b++) { int v = g_bsum[b]; g_bsum[b] = acc; acc += v; }
}

__global__ void k_scan3() {
    int t = threadIdx.x;
    int i = blockIdx.x * 1024 + t;
    if (i < N_NODES) {
        int v = g_incl[i] - g_deg[i] + g_bsum[blockIdx.x];   // exclusive
        g_rowptr[i] = v;
        g_cursor[i] = v;
    }
    if (i == 0) g_rowptr[N_NODES] = N_EDGES;
}

__global__ void k_scatter(const int* __restrict__ ei) {
    int e = blockIdx.x * blockDim.x + threadIdx.x;
    if (e < N_EDGES) {
        int s = ei[e];
        int d = ei[N_EDGES + e];
        int pos = atomicAdd(&g_cursor[d], 1);
        g_srcidx[pos] = s;
    }
}

// ---------------- GEMM: out[row] = scale[row] * (X[row] @ W) (+bias)(+relu) -
// One thread per row, all NOUT columns accumulated in registers; W staged in
// shared memory (broadcast LDS across the warp, conflict-free).
template <int NOUT>
__global__ void k_gemm(const float* __restrict__ X, const float* __restrict__ W,
                       const float* __restrict__ scale, const float* __restrict__ bias,
                       float* __restrict__ out, int M, int relu) {
    constexpr int NJ = NOUT / 4;
    extern __shared__ float4 Ws4[];                 // [128 * NJ]
    int t = threadIdx.x;
    const float4* W4 = (const float4*)W;
    for (int i = t; i < 128 * NJ; i += 256) Ws4[i] = W4[i];
    __syncthreads();

    int row = blockIdx.x * 256 + t;
    if (row >= M) return;

    float4 acc[NJ];
#pragma unroll
    for (int j = 0; j < NJ; j++) acc[j] = make_float4(0.f, 0.f, 0.f, 0.f);

    const float4* x4 = (const float4*)X + (size_t)row * 32;
#pragma unroll 4
    for (int k4 = 0; k4 < 32; k4++) {
        float4 xv = __ldg(x4 + k4);
#pragma unroll
        for (int u = 0; u < 4; u++) {
            float xu = (u == 0) ? xv.x : (u == 1) ? xv.y : (u == 2) ? xv.z : xv.w;
            const float4* wr = Ws4 + (k4 * 4 + u) * NJ;
#pragma unroll
            for (int j = 0; j < NJ; j++) {
                float4 w = wr[j];
                acc[j].x = fmaf(xu, w.x, acc[j].x);
                acc[j].y = fmaf(xu, w.y, acc[j].y);
                acc[j].z = fmaf(xu, w.z, acc[j].z);
                acc[j].w = fmaf(xu, w.w, acc[j].w);
            }
        }
    }

    float s = scale ? scale[row] : 1.0f;
    float4* out4 = (float4*)out + (size_t)row * NJ;
#pragma unroll
    for (int j = 0; j < NJ; j++) {
        float4 v = acc[j];
        v.x *= s; v.y *= s; v.z *= s; v.w *= s;
        if (bias) {
            float4 b = ((const float4*)bias)[j];
            v.x += b.x; v.y += b.y; v.z += b.z; v.w += b.w;
        }
        if (relu) {
            v.x = fmaxf(v.x, 0.f); v.y = fmaxf(v.y, 0.f);
            v.z = fmaxf(v.z, 0.f); v.w = fmaxf(v.w, 0.f);
        }
        out4[j] = v;
    }
}

// ---------------- aggregation: one warp per destination node ----------------
// acc = hs[d] (self loop) + sum over CSR in-edges of hs[src]
// out[d] = relu(dinv[d] * acc + bias)
__global__ void k_agg(const float4* __restrict__ hs, const float* __restrict__ bias,
                      float4* __restrict__ out) {
    int warp = (blockIdx.x * blockDim.x + threadIdx.x) >> 5;
    int lane = threadIdx.x & 31;
    if (warp >= N_NODES) return;

    float4 acc = hs[(size_t)warp * 32 + lane];      // self loop
    int s0 = g_rowptr[warp];
    int s1 = g_rowptr[warp + 1];
    int i = s0;
    for (; i + 4 <= s1; i += 4) {
        int e0 = g_srcidx[i + 0];
        int e1 = g_srcidx[i + 1];
        int e2 = g_srcidx[i + 2];
        int e3 = g_srcidx[i + 3];
        float4 v0 = hs[(size_t)e0 * 32 + lane];
        float4 v1 = hs[(size_t)e1 * 32 + lane];
        float4 v2 = hs[(size_t)e2 * 32 + lane];
        float4 v3 = hs[(size_t)e3 * 32 + lane];
        acc.x += v0.x + v1.x + v2.x + v3.x;
        acc.y += v0.y + v1.y + v2.y + v3.y;
        acc.z += v0.z + v1.z + v2.z + v3.z;
        acc.w += v0.w + v1.w + v2.w + v3.w;
    }
    for (; i < s1; i++) {
        int e = g_srcidx[i];
        float4 v = hs[(size_t)e * 32 + lane];
        acc.x += v.x; acc.y += v.y; acc.z += v.z; acc.w += v.w;
    }

    float dv = g_dinv[warp];
    float4 b = ((const float4*)bias)[lane];
    float4 o;
    o.x = fmaxf(fmaf(dv, acc.x, b.x), 0.f);
    o.y = fmaxf(fmaf(dv, acc.y, b.y), 0.f);
    o.z = fmaxf(fmaf(dv, acc.z, b.z), 0.f);
    o.w = fmaxf(fmaf(dv, acc.w, b.w), 0.f);
    out[(size_t)warp * 32 + lane] = o;
}

// ---------------- global mean pool (batch is sorted) ------------------------
__global__ void k_pool(const float* __restrict__ h, const int* __restrict__ batch) {
    int g = blockIdx.x;       // graph id
    int c = threadIdx.x;      // channel 0..127

    // lower_bound(batch, g) and lower_bound(batch, g+1)
    int lo = 0, hi = N_NODES;
    while (lo < hi) { int mid = (lo + hi) >> 1; if (batch[mid] < g) lo = mid + 1; else hi = mid; }
    int start = lo;
    lo = start; hi = N_NODES;
    while (lo < hi) { int mid = (lo + hi) >> 1; if (batch[mid] < g + 1) lo = mid + 1; else hi = mid; }
    int end = lo;

    float acc = 0.f;
    for (int r = start; r < end; r++) acc += h[(size_t)r * HID + c];
    int cnt = end - start;
    g_pool[g * HID + c] = acc / (float)(cnt > 0 ? cnt : 1);
}

// ---------------- launch -----------------------------------------------------
extern "C" void kernel_launch(void* const* d_in, const int* in_sizes, int n_in,
                              void* d_out, int out_size) {
    const float* x   = (const float*)d_in[0];
    const int*   ei  = (const int*)d_in[1];     // [2, E] int32 (jax default x64=off)
    const int*   bat = (const int*)d_in[2];
    const float* W1  = (const float*)d_in[3];
    const float* b1  = (const float*)d_in[4];
    const float* W2  = (const float*)d_in[5];
    const float* b2  = (const float*)d_in[6];
    const float* W3  = (const float*)d_in[7];
    const float* b3  = (const float*)d_in[8];
    const float* W4  = (const float*)d_in[9];
    const float* b4  = (const float*)d_in[10];
    float* out = (float*)d_out;

    // scratch pointers (device globals)
    float4* hs;  float4* h2;  float* pool; float* mlp; float* dinv;
    cudaGetSymbolAddress((void**)&hs,   g_hs);
    cudaGetSymbolAddress((void**)&h2,   g_h2);
    cudaGetSymbolAddress((void**)&pool, g_pool);
    cudaGetSymbolAddress((void**)&mlp,  g_mlp);
    cudaGetSymbolAddress((void**)&dinv, g_dinv);

    cudaFuncSetAttribute(k_gemm<HID>,    cudaFuncAttributeMaxDynamicSharedMemorySize, 128 * HID * 4);
    cudaFuncSetAttribute(k_gemm<OUT_CH>, cudaFuncAttributeMaxDynamicSharedMemorySize, 128 * OUT_CH * 4);

    const int TB = 256;
    int nbN = (N_NODES + TB - 1) / TB;
    int nbE = (N_EDGES + TB - 1) / TB;
    int nbAgg = (N_NODES * 32 + TB - 1) / TB;   // one warp per node
    int nbGemmN = (N_NODES + 255) / 256;
    int nbGemmG = (N_GRAPHS + 255) / 256;

    // CSR build (per call; edge_index is an input so no caching)
    k_zero_deg<<<nbN, TB>>>();
    k_count<<<nbE, TB>>>(ei);
    k_dinv<<<nbN, TB>>>();
    k_scan1<<<NB_SCAN, 1024>>>();
    k_scan2<<<1, 1>>>(NB_SCAN);
    k_scan3<<<NB_SCAN, 1024>>>();
    k_scatter<<<nbE, TB>>>(ei);

    // conv1: hs = dinv * (x @ W1); h2 = relu(dinv * (A+I)-gather(hs) + b1)
    k_gemm<HID><<<nbGemmN, 256, 128 * HID * 4>>>(x, W1, dinv, nullptr, (float*)hs, N_NODES, 0);
    k_agg<<<nbAgg, TB>>>(hs, b1, h2);

    // conv2
    k_gemm<HID><<<nbGemmN, 256, 128 * HID * 4>>>((const float*)h2, W2, dinv, nullptr, (float*)hs, N_NODES, 0);
    k_agg<<<nbAgg, TB>>>(hs, b2, h2);

    // pool
    k_pool<<<N_GRAPHS, HID>>>((const float*)h2, bat);

    // MLP head
    k_gemm<HID><<<nbGemmG, 256, 128 * HID * 4>>>(pool, W3, nullptr, b3, mlp, N_GRAPHS, 1);
    k_gemm<OUT_CH><<<nbGemmG, 256, 128 * OUT_CH * 4>>>(mlp, W4, nullptr, b4, out, N_GRAPHS, 0);
}

// round 3
// speedup vs baseline: 1.0874x; 1.0874x over previous
#include <cuda_runtime.h>
#include <cuda_fp16.h>

#define N_NODES  100000
#define N_EDGES  1600000
#define IN_CH    128
#define HID      128
#define OUT_CH   64
#define N_GRAPHS 512

static const int NB_SCAN = (N_NODES + 1023) / 1024;   // 98

// ---------------- scratch (device globals: no allocation allowed) ----------
__device__ int    g_deg[N_NODES];
__device__ int    g_incl[N_NODES];
__device__ int    g_bsum[128];
__device__ int    g_rowptr[N_NODES + 1];
__device__ int    g_cursor[N_NODES];
__device__ int    g_srcidx[N_EDGES];
__device__ float  g_dinv[N_NODES];
__device__ uint2  g_hs[N_NODES * 32];          // fp16 features: 128 half = 32 uint2/row
__device__ float4 g_h2[N_NODES * (HID / 4)];   // conv output (fp32)
__device__ float  g_pool[N_GRAPHS * HID];
__device__ float  g_mlp [N_GRAPHS * HID];

// ---------------- degree / CSR build ---------------------------------------
__global__ void k_zero_deg() {
    int i = blockIdx.x * blockDim.x + threadIdx.x;
    if (i < N_NODES) g_deg[i] = 0;
}

__global__ void k_count(const int* __restrict__ ei) {
    int e = blockIdx.x * blockDim.x + threadIdx.x;
    if (e < N_EDGES) {
        int d = ei[N_EDGES + e];
        atomicAdd(&g_deg[d], 1);
    }
}

__global__ void k_scan1() {
    __shared__ int s[1024];
    int t = threadIdx.x;
    int i = blockIdx.x * 1024 + t;
    int v = (i < N_NODES) ? g_deg[i] : 0;
    s[t] = v;
    __syncthreads();
    for (int off = 1; off < 1024; off <<= 1) {
        int a = (t >= off) ? s[t - off] : 0;
        __syncthreads();
        s[t] += a;
        __syncthreads();
    }
    if (i < N_NODES) g_incl[i] = s[t];
    if (t == 1023) g_bsum[blockIdx.x] = s[1023];
}

__global__ void k_scan2(int nb) {
    // block-parallel exclusive scan over <=128 block sums
    __shared__ int s[128];
    int t = threadIdx.x;
    int v = (t < nb) ? g_bsum[t] : 0;
    s[t] = v;
    __syncthreads();
    for (int off = 1; off < 128; off <<= 1) {
        int a = (t >= off) ? s[t - off] : 0;
        __syncthreads();
        s[t] += a;
        __syncthreads();
    }
    if (t < nb) g_bsum[t] = s[t] - v;   // exclusive
}

__global__ void k_scan3() {
    int t = threadIdx.x;
    int i = blockIdx.x * 1024 + t;
    if (i < N_NODES) {
        int d = g_deg[i];
        int v = g_incl[i] - d + g_bsum[blockIdx.x];   // exclusive
        g_rowptr[i] = v;
        g_cursor[i] = v;
        g_dinv[i]   = rsqrtf((float)(d + 1));          // +1: self loop
    }
    if (i == 0) g_rowptr[N_NODES] = N_EDGES;
}

__global__ void k_scatter(const int* __restrict__ ei) {
    int e = blockIdx.x * blockDim.x + threadIdx.x;
    if (e < N_EDGES) {
        int s = ei[e];
        int d = ei[N_EDGES + e];
        int pos = atomicAdd(&g_cursor[d], 1);
        g_srcidx[pos] = s;
    }
}

// ---------------- GEMM: out[row] = scale[row] * (X[row] @ W) (+bias)(+relu) -
// One thread per row, all NOUT columns in registers; W staged in smem
// (broadcast LDS, conflict-free). HALF_OUT packs the row to fp16.
template <int NOUT, bool HALF_OUT>
__global__ void __launch_bounds__(256) k_gemm(
        const float* __restrict__ X, const float* __restrict__ W,
        const float* __restrict__ scale, const float* __restrict__ bias,
        void* __restrict__ out, int M, int relu) {
    constexpr int NJ = NOUT / 4;
    extern __shared__ float4 Ws4[];                 // [128 * NJ]
    int t = threadIdx.x;
    const float4* W4 = (const float4*)W;
    for (int i = t; i < 128 * NJ; i += 256) Ws4[i] = W4[i];
    __syncthreads();

    int row = blockIdx.x * 256 + t;
    if (row >= M) return;

    float4 acc[NJ];
#pragma unroll
    for (int j = 0; j < NJ; j++) acc[j] = make_float4(0.f, 0.f, 0.f, 0.f);

    const float4* x4 = (const float4*)X + (size_t)row * 32;
#pragma unroll 4
    for (int k4 = 0; k4 < 32; k4++) {
        float4 xv = __ldg(x4 + k4);
#pragma unroll
        for (int u = 0; u < 4; u++) {
            float xu = (u == 0) ? xv.x : (u == 1) ? xv.y : (u == 2) ? xv.z : xv.w;
            const float4* wr = Ws4 + (k4 * 4 + u) * NJ;
#pragma unroll
            for (int j = 0; j < NJ; j++) {
                float4 w = wr[j];
                acc[j].x = fmaf(xu, w.x, acc[j].x);
                acc[j].y = fmaf(xu, w.y, acc[j].y);
                acc[j].z = fmaf(xu, w.z, acc[j].z);
                acc[j].w = fmaf(xu, w.w, acc[j].w);
            }
        }
    }

    float s = scale ? scale[row] : 1.0f;
#pragma unroll
    for (int j = 0; j < NJ; j++) {
        acc[j].x *= s; acc[j].y *= s; acc[j].z *= s; acc[j].w *= s;
        if (bias) {
            float4 b = ((const float4*)bias)[j];
            acc[j].x += b.x; acc[j].y += b.y; acc[j].z += b.z; acc[j].w += b.w;
        }
        if (relu) {
            acc[j].x = fmaxf(acc[j].x, 0.f); acc[j].y = fmaxf(acc[j].y, 0.f);
            acc[j].z = fmaxf(acc[j].z, 0.f); acc[j].w = fmaxf(acc[j].w, 0.f);
        }
    }

    if (HALF_OUT) {
        uint4* o = (uint4*)out + (size_t)row * (NOUT / 8);
#pragma unroll
        for (int jj = 0; jj < NJ / 2; jj++) {
            float4 a = acc[2 * jj], b = acc[2 * jj + 1];
            __half2 h0 = __floats2half2_rn(a.x, a.y);
            __half2 h1 = __floats2half2_rn(a.z, a.w);
            __half2 h2v = __floats2half2_rn(b.x, b.y);
            __half2 h3 = __floats2half2_rn(b.z, b.w);
            uint4 u;
            u.x = *(unsigned*)&h0; u.y = *(unsigned*)&h1;
            u.z = *(unsigned*)&h2v; u.w = *(unsigned*)&h3;
            o[jj] = u;
        }
    } else {
        float4* o = (float4*)out + (size_t)row * NJ;
#pragma unroll
        for (int j = 0; j < NJ; j++) o[j] = acc[j];
    }
}

// ---------------- aggregation: one warp per destination node ----------------
// acc = hs[d] (self loop) + sum over CSR in-edges of hs[src]   (hs is fp16)
// out[d] = relu(dinv[d] * acc + bias)
__device__ __forceinline__ void acc_h4(float4& acc, uint2 u) {
    __half2 a = *(__half2*)&u.x;
    __half2 b = *(__half2*)&u.y;
    float2 fa = __half22float2(a);
    float2 fb = __half22float2(b);
    acc.x += fa.x; acc.y += fa.y; acc.z += fb.x; acc.w += fb.y;
}

__global__ void __launch_bounds__(256) k_agg(
        const uint2* __restrict__ hs, const float* __restrict__ bias,
        float4* __restrict__ out) {
    int warp = (blockIdx.x * blockDim.x + threadIdx.x) >> 5;
    int lane = threadIdx.x & 31;
    if (warp >= N_NODES) return;

    float4 acc = make_float4(0.f, 0.f, 0.f, 0.f);
    acc_h4(acc, hs[(size_t)warp * 32 + lane]);      // self loop

    int s0 = g_rowptr[warp];
    int s1 = g_rowptr[warp + 1];
    int i = s0;
    for (; i + 8 <= s1; i += 8) {
        int e[8];
#pragma unroll
        for (int q = 0; q < 8; q++) e[q] = g_srcidx[i + q];
        uint2 v[8];
#pragma unroll
        for (int q = 0; q < 8; q++) v[q] = hs[(size_t)e[q] * 32 + lane];
#pragma unroll
        for (int q = 0; q < 8; q++) acc_h4(acc, v[q]);
    }
    for (; i < s1; i++) {
        int e = g_srcidx[i];
        acc_h4(acc, hs[(size_t)e * 32 + lane]);
    }

    float dv = g_dinv[warp];
    float4 b = ((const float4*)bias)[lane];
    float4 o;
    o.x = fmaxf(fmaf(dv, acc.x, b.x), 0.f);
    o.y = fmaxf(fmaf(dv, acc.y, b.y), 0.f);
    o.z = fmaxf(fmaf(dv, acc.z, b.z), 0.f);
    o.w = fmaxf(fmaf(dv, acc.w, b.w), 0.f);
    out[(size_t)warp * 32 + lane] = o;
}

// ---------------- global mean pool (batch is sorted) ------------------------
__global__ void k_pool(const float* __restrict__ h, const int* __restrict__ batch) {
    int g = blockIdx.x;       // graph id
    int c = threadIdx.x;      // channel 0..127

    int lo = 0, hi = N_NODES;
    while (lo < hi) { int mid = (lo + hi) >> 1; if (batch[mid] < g) lo = mid + 1; else hi = mid; }
    int start = lo;
    lo = start; hi = N_NODES;
    while (lo < hi) { int mid = (lo + hi) >> 1; if (batch[mid] < g + 1) lo = mid + 1; else hi = mid; }
    int end = lo;

    float acc = 0.f;
    for (int r = start; r < end; r++) acc += h[(size_t)r * HID + c];
    int cnt = end - start;
    g_pool[g * HID + c] = acc / (float)(cnt > 0 ? cnt : 1);
}

// ---------------- launch -----------------------------------------------------
extern "C" void kernel_launch(void* const* d_in, const int* in_sizes, int n_in,
                              void* d_out, int out_size) {
    const float* x   = (const float*)d_in[0];
    const int*   ei  = (const int*)d_in[1];     // [2, E] int32
    const int*   bat = (const int*)d_in[2];
    const float* W1  = (const float*)d_in[3];
    const float* b1  = (const float*)d_in[4];
    const float* W2  = (const float*)d_in[5];
    const float* b2  = (const float*)d_in[6];
    const float* W3  = (const float*)d_in[7];
    const float* b3  = (const float*)d_in[8];
    const float* W4  = (const float*)d_in[9];
    const float* b4  = (const float*)d_in[10];
    float* out = (float*)d_out;

    uint2* hs;  float4* h2;  float* pool; float* mlp; float* dinv;
    cudaGetSymbolAddress((void**)&hs,   g_hs);
    cudaGetSymbolAddress((void**)&h2,   g_h2);
    cudaGetSymbolAddress((void**)&pool, g_pool);
    cudaGetSymbolAddress((void**)&mlp,  g_mlp);
    cudaGetSymbolAddress((void**)&dinv, g_dinv);

    cudaFuncSetAttribute(k_gemm<HID, true>,     cudaFuncAttributeMaxDynamicSharedMemorySize, 128 * HID * 4);
    cudaFuncSetAttribute(k_gemm<HID, false>,    cudaFuncAttributeMaxDynamicSharedMemorySize, 128 * HID * 4);
    cudaFuncSetAttribute(k_gemm<OUT_CH, false>, cudaFuncAttributeMaxDynamicSharedMemorySize, 128 * OUT_CH * 4);

    const int TB = 256;
    int nbN = (N_NODES + TB - 1) / TB;
    int nbE = (N_EDGES + TB - 1) / TB;
    int nbAgg = (N_NODES * 32 + TB - 1) / TB;   // one warp per node
    int nbGemmN = (N_NODES + 255) / 256;
    int nbGemmG = (N_GRAPHS + 255) / 256;

    // CSR build
    k_zero_deg<<<nbN, TB>>>();
    k_count<<<nbE, TB>>>(ei);
    k_scan1<<<NB_SCAN, 1024>>>();
    k_scan2<<<1, 128>>>(NB_SCAN);
    k_scan3<<<NB_SCAN, 1024>>>();
    k_scatter<<<nbE, TB>>>(ei);

    // conv1: hs = fp16(dinv * (x @ W1)); h2 = relu(dinv * gather(hs) + b1)
    k_gemm<HID, true><<<nbGemmN, 256, 128 * HID * 4>>>(x, W1, dinv, nullptr, hs, N_NODES, 0);
    k_agg<<<nbAgg, TB>>>(hs, b1, h2);

    // conv2
    k_gemm<HID, true><<<nbGemmN, 256, 128 * HID * 4>>>((const float*)h2, W2, dinv, nullptr, hs, N_NODES, 0);
    k_agg<<<nbAgg, TB>>>(hs, b2, h2);

    // pool
    k_pool<<<N_GRAPHS, HID>>>((const float*)h2, bat);

    // MLP head
    k_gemm<HID, false><<<nbGemmG, 256, 128 * HID * 4>>>(pool, W3, nullptr, b3, mlp, N_GRAPHS, 1);
    k_gemm<OUT_CH, false><<<nbGemmG, 256, 128 * OUT_CH * 4>>>(mlp, W4, nullptr, b4, out, N_GRAPHS, 0);
}

// round 5
// speedup vs baseline: 2.0357x; 1.8720x over previous
#include <cuda_runtime.h>
#include <cuda_fp16.h>
#include <cstdint>

#define N_NODES  100000
#define N_EDGES  1600000
#define IN_CH    128
#define HID      128
#define OUT_CH   64
#define N_GRAPHS 512

static const int NB_SCAN = (N_NODES + 1023) / 1024;   // 98

// ---------------- scratch (device globals) ----------------------------------
__device__ int    g_deg[N_NODES];
__device__ int    g_incl[N_NODES];
__device__ int    g_bsum[128];
__device__ int    g_rowptr[N_NODES + 1];
__device__ int    g_cursor[N_NODES];
__device__ int    g_srcidx[N_EDGES];
__device__ float  g_dinv[N_NODES];
__device__ __half g_hs[(size_t)N_NODES * HID];     // fp16 features (gather source)
__device__ float4 g_h2[N_NODES * (HID / 4)];       // conv output (fp32)
__device__ float  g_pool[N_GRAPHS * HID];
__device__ float  g_mlp [N_GRAPHS * HID];

// ---------------- degree / CSR build ---------------------------------------
__global__ void k_zero_deg() {
    int i = blockIdx.x * blockDim.x + threadIdx.x;
    if (i < N_NODES) g_deg[i] = 0;
}

__global__ void k_count(const int* __restrict__ ei) {
    int e = blockIdx.x * blockDim.x + threadIdx.x;
    if (e < N_EDGES) atomicAdd(&g_deg[ei[N_EDGES + e]], 1);
}

__global__ void k_scan1() {
    __shared__ int s[1024];
    int t = threadIdx.x;
    int i = blockIdx.x * 1024 + t;
    int v = (i < N_NODES) ? g_deg[i] : 0;
    s[t] = v;
    __syncthreads();
    for (int off = 1; off < 1024; off <<= 1) {
        int a = (t >= off) ? s[t - off] : 0;
        __syncthreads();
        s[t] += a;
        __syncthreads();
    }
    if (i < N_NODES) g_incl[i] = s[t];
    if (t == 1023) g_bsum[blockIdx.x] = s[1023];
}

__global__ void k_scan2(int nb) {
    __shared__ int s[128];
    int t = threadIdx.x;
    int v = (t < nb) ? g_bsum[t] : 0;
    s[t] = v;
    __syncthreads();
    for (int off = 1; off < 128; off <<= 1) {
        int a = (t >= off) ? s[t - off] : 0;
        __syncthreads();
        s[t] += a;
        __syncthreads();
    }
    if (t < nb) g_bsum[t] = s[t] - v;   // exclusive
}

__global__ void k_scan3() {
    int t = threadIdx.x;
    int i = blockIdx.x * 1024 + t;
    if (i < N_NODES) {
        int d = g_deg[i];
        int v = g_incl[i] - d + g_bsum[blockIdx.x];
        g_rowptr[i] = v;
        g_cursor[i] = v;
        g_dinv[i]   = rsqrtf((float)(d + 1));
    }
    if (i == 0) g_rowptr[N_NODES] = N_EDGES;
}

__global__ void k_scatter(const int* __restrict__ ei) {
    int e = blockIdx.x * blockDim.x + threadIdx.x;
    if (e < N_EDGES) {
        int s = ei[e];
        int d = ei[N_EDGES + e];
        g_srcidx[atomicAdd(&g_cursor[d], 1)] = s;
    }
}

// ---------------- tensor-core GEMM (K=128 fixed) ----------------------------
// out[row] = epi( scale[row] * (X[row] @ W) ), via mma.sync m16n8k16 fp16->fp32.
// Block: 256 threads / 8 warps, 128-row tile. A staged fp32->fp16 in smem,
// W transposed to (n,k) fp16 in smem (col-major B for .row.col mma).
template <int NOUT, bool HALF_OUT>
__global__ void __launch_bounds__(256) k_gemm_mma(
        const float* __restrict__ X, const float* __restrict__ W,
        const float* __restrict__ scale, const float* __restrict__ bias,
        void* __restrict__ out, int M, int relu) {
    constexpr int NT = NOUT / 8;
    constexpr int AS = 136;                       // padded stride (halves)
    extern __shared__ __half sm[];
    __half* Asm = sm;                             // [128][AS]
    __half* Bt  = sm + 128 * AS;                  // [NOUT][AS]
    int t = threadIdx.x;
    int rowBase = blockIdx.x * 128;

    // stage A (fp32 -> fp16), zero-fill OOB rows
    for (int idx = t; idx < 128 * 32; idx += 256) {
        int r = idx >> 5, c4 = idx & 31;
        float4 v = make_float4(0.f, 0.f, 0.f, 0.f);
        int gr = rowBase + r;
        if (gr < M) v = ((const float4*)X)[(size_t)gr * 32 + c4];
        *(__half2*)&Asm[r * AS + c4 * 4]     = __floats2half2_rn(v.x, v.y);
        *(__half2*)&Asm[r * AS + c4 * 4 + 2] = __floats2half2_rn(v.z, v.w);
    }
    // stage W transposed: Bt[n][k] = W[k][n]
    for (int idx = t; idx < 128 * NOUT; idx += 256) {
        int k = idx / NOUT, n = idx % NOUT;
        Bt[n * AS + k] = __float2half_rn(W[idx]);
    }
    __syncthreads();

    int w = t >> 5, lane = t & 31;
    int g = lane >> 2, s = lane & 3;
    int strip = w * 16;

    float acc[NT][4];
#pragma unroll
    for (int nt = 0; nt < NT; nt++)
#pragma unroll
        for (int q = 0; q < 4; q++) acc[nt][q] = 0.f;

    const __half* Arow0 = &Asm[(strip + g) * AS + s * 2];
    const __half* Arow1 = Arow0 + 8 * AS;
#pragma unroll
    for (int ks = 0; ks < 8; ks++) {
        int kb = ks * 16;
        unsigned a0 = *(const unsigned*)(Arow0 + kb);
        unsigned a1 = *(const unsigned*)(Arow1 + kb);
        unsigned a2 = *(const unsigned*)(Arow0 + kb + 8);
        unsigned a3 = *(const unsigned*)(Arow1 + kb + 8);
#pragma unroll
        for (int nt = 0; nt < NT; nt++) {
            const __half* Bp = &Bt[(nt * 8 + g) * AS + kb + s * 2];
            unsigned b0 = *(const unsigned*)(Bp);
            unsigned b1 = *(const unsigned*)(Bp + 8);
            asm volatile(
                "mma.sync.aligned.m16n8k16.row.col.f32.f16.f16.f32 "
                "{%0,%1,%2,%3}, {%4,%5,%6,%7}, {%8,%9}, {%0,%1,%2,%3};"
                : "+f"(acc[nt][0]), "+f"(acc[nt][1]), "+f"(acc[nt][2]), "+f"(acc[nt][3])
                : "r"(a0), "r"(a1), "r"(a2), "r"(a3), "r"(b0), "r"(b1));
        }
    }

    // epilogue
    int gr0 = rowBase + strip + g;
    int gr1 = gr0 + 8;
    float dv0 = 1.f, dv1 = 1.f;
    if (scale) {
        dv0 = (gr0 < M) ? scale[gr0] : 0.f;
        dv1 = (gr1 < M) ? scale[gr1] : 0.f;
    }
#pragma unroll
    for (int nt = 0; nt < NT; nt++) {
        int col = nt * 8 + s * 2;
        float bx = 0.f, by = 0.f;
        if (bias) { bx = bias[col]; by = bias[col + 1]; }
        float v00 = fmaf(acc[nt][0], dv0, bx), v01 = fmaf(acc[nt][1], dv0, by);
        float v10 = fmaf(acc[nt][2], dv1, bx), v11 = fmaf(acc[nt][3], dv1, by);
        if (relu) {
            v00 = fmaxf(v00, 0.f); v01 = fmaxf(v01, 0.f);
            v10 = fmaxf(v10, 0.f); v11 = fmaxf(v11, 0.f);
        }
        if (HALF_OUT) {
            __half* hp = (__half*)out;
            if (gr0 < M) *(__half2*)&hp[(size_t)gr0 * NOUT + col] = __floats2half2_rn(v00, v01);
            if (gr1 < M) *(__half2*)&hp[(size_t)gr1 * NOUT + col] = __floats2half2_rn(v10, v11);
        } else {
            float* fp = (float*)out;
            if (gr0 < M) *(float2*)&fp[(size_t)gr0 * NOUT + col] = make_float2(v00, v01);
            if (gr1 < M) *(float2*)&fp[(size_t)gr1 * NOUT + col] = make_float2(v10, v11);
        }
    }
}

// ---------------- aggregation: warp per node, 2 half-warps, LDG.128 ---------
__device__ __forceinline__ void acc8(float* a, uint4 u) {
    const __half2* h = (const __half2*)&u;
#pragma unroll
    for (int j = 0; j < 4; j++) {
        float2 f = __half22float2(h[j]);
        a[2 * j]     += f.x;
        a[2 * j + 1] += f.y;
    }
}

__global__ void __launch_bounds__(256) k_agg(
        const uint4* __restrict__ hs, const float* __restrict__ bias,
        float4* __restrict__ out) {
    int warp = (blockIdx.x * blockDim.x + threadIdx.x) >> 5;
    int lane = threadIdx.x & 31;
    if (warp >= N_NODES) return;
    int hw = lane >> 4, c = lane & 15;     // half-warp id, 16B chunk id

    float a[8] = {0.f, 0.f, 0.f, 0.f, 0.f, 0.f, 0.f, 0.f};
    if (hw == 0) acc8(a, hs[(size_t)warp * 16 + c]);   // self loop

    int s0 = g_rowptr[warp];
    int s1 = g_rowptr[warp + 1];
    int i = s0 + hw;                       // half-warp hw takes edges s0+hw, +2, ...
    for (; i + 6 < s1; i += 8) {           // 4 edges per half-warp in flight
        int e0 = g_srcidx[i];
        int e1 = g_srcidx[i + 2];
        int e2 = g_srcidx[i + 4];
        int e3 = g_srcidx[i + 6];
        uint4 v0 = hs[(size_t)e0 * 16 + c];
        uint4 v1 = hs[(size_t)e1 * 16 + c];
        uint4 v2 = hs[(size_t)e2 * 16 + c];
        uint4 v3 = hs[(size_t)e3 * 16 + c];
        acc8(a, v0); acc8(a, v1); acc8(a, v2); acc8(a, v3);
    }
    for (; i < s1; i += 2) acc8(a, hs[(size_t)g_srcidx[i] * 16 + c]);

    // combine the two half-warps (lane l += lane l+16)
#pragma unroll
    for (int q = 0; q < 8; q++) a[q] += __shfl_down_sync(0xffffffffu, a[q], 16);

    if (hw == 0) {
        float dv = g_dinv[warp];
        float4 b0 = ((const float4*)bias)[2 * c];
        float4 b1 = ((const float4*)bias)[2 * c + 1];
        float4 o0, o1;
        o0.x = fmaxf(fmaf(dv, a[0], b0.x), 0.f);
        o0.y = fmaxf(fmaf(dv, a[1], b0.y), 0.f);
        o0.z = fmaxf(fmaf(dv, a[2], b0.z), 0.f);
        o0.w = fmaxf(fmaf(dv, a[3], b0.w), 0.f);
        o1.x = fmaxf(fmaf(dv, a[4], b1.x), 0.f);
        o1.y = fmaxf(fmaf(dv, a[5], b1.y), 0.f);
        o1.z = fmaxf(fmaf(dv, a[6], b1.z), 0.f);
        o1.w = fmaxf(fmaf(dv, a[7], b1.w), 0.f);
        out[(size_t)warp * 32 + 2 * c]     = o0;
        out[(size_t)warp * 32 + 2 * c + 1] = o1;
    }
}

// ---------------- global mean pool (batch sorted) ----------------------------
__global__ void k_pool(const float* __restrict__ h, const int* __restrict__ batch) {
    int g = blockIdx.x;
    int c = threadIdx.x;

    int lo = 0, hi = N_NODES;
    while (lo < hi) { int mid = (lo + hi) >> 1; if (batch[mid] < g) lo = mid + 1; else hi = mid; }
    int start = lo;
    lo = start; hi = N_NODES;
    while (lo < hi) { int mid = (lo + hi) >> 1; if (batch[mid] < g + 1) lo = mid + 1; else hi = mid; }
    int end = lo;

    float acc = 0.f;
    for (int r = start; r < end; r++) acc += h[(size_t)r * HID + c];
    int cnt = end - start;
    g_pool[g * HID + c] = acc / (float)(cnt > 0 ? cnt : 1);
}

// ---------------- launch ------------------------------------------------------
extern "C" void kernel_launch(void* const* d_in, const int* in_sizes, int n_in,
                              void* d_out, int out_size) {
    const float* x   = (const float*)d_in[0];
    const int*   ei  = (const int*)d_in[1];
    const int*   bat = (const int*)d_in[2];
    const float* W1  = (const float*)d_in[3];
    const float* b1  = (const float*)d_in[4];
    const float* W2  = (const float*)d_in[5];
    const float* b2  = (const float*)d_in[6];
    const float* W3  = (const float*)d_in[7];
    const float* b3  = (const float*)d_in[8];
    const float* W4  = (const float*)d_in[9];
    const float* b4  = (const float*)d_in[10];
    float* out = (float*)d_out;

    __half* hs; float4* h2; float* pool; float* mlp; float* dinv;
    cudaGetSymbolAddress((void**)&hs,   g_hs);
    cudaGetSymbolAddress((void**)&h2,   g_h2);
    cudaGetSymbolAddress((void**)&pool, g_pool);
    cudaGetSymbolAddress((void**)&mlp,  g_mlp);
    cudaGetSymbolAddress((void**)&dinv, g_dinv);

    const int SM128 = (128 + 128) * 136 * 2;   // 69632 B
    const int SM64  = (128 + 64)  * 136 * 2;   // 52224 B
    cudaFuncSetAttribute(k_gemm_mma<HID, true>,     cudaFuncAttributeMaxDynamicSharedMemorySize, SM128);
    cudaFuncSetAttribute(k_gemm_mma<HID, false>,    cudaFuncAttributeMaxDynamicSharedMemorySize, SM128);
    cudaFuncSetAttribute(k_gemm_mma<OUT_CH, false>, cudaFuncAttributeMaxDynamicSharedMemorySize, SM64);

    const int TB = 256;
    int nbN = (N_NODES + TB - 1) / TB;
    int nbE = (N_EDGES + TB - 1) / TB;
    int nbAgg = (N_NODES * 32 + TB - 1) / TB;
    int nbGemmN = (N_NODES + 127) / 128;    // 782
    int nbGemmG = (N_GRAPHS + 127) / 128;   // 4

    // CSR build
    k_zero_deg<<<nbN, TB>>>();
    k_count<<<nbE, TB>>>(ei);
    k_scan1<<<NB_SCAN, 1024>>>();
    k_scan2<<<1, 128>>>(NB_SCAN);
    k_scan3<<<NB_SCAN, 1024>>>();
    k_scatter<<<nbE, TB>>>(ei);

    // conv1: hs = fp16(dinv * (x @ W1)); h2 = relu(dinv * gather(hs) + b1)
    k_gemm_mma<HID, true><<<nbGemmN, 256, SM128>>>(x, W1, dinv, nullptr, hs, N_NODES, 0);
    k_agg<<<nbAgg, TB>>>((const uint4*)hs, b1, h2);

    // conv2
    k_gemm_mma<HID, true><<<nbGemmN, 256, SM128>>>((const float*)h2, W2, dinv, nullptr, hs, N_NODES, 0);
    k_agg<<<nbAgg, TB>>>((const uint4*)hs, b2, h2);

    // pool
    k_pool<<<N_GRAPHS, HID>>>((const float*)h2, bat);

    // MLP head (tensor-core path too)
    k_gemm_mma<HID, false><<<nbGemmG, 256, SM128>>>(pool, W3, nullptr, b3, mlp, N_GRAPHS, 1);
    k_gemm_mma<OUT_CH, false><<<nbGemmG, 256, SM64>>>(mlp, W4, nullptr, b4, out, N_GRAPHS, 0);
}